// round 9
// baseline (speedup 1.0000x reference)
#include <cuda_runtime.h>
#include <cuda_fp16.h>
#include <math.h>
#include <stdint.h>

// Problem dims (fixed by the dataset)
#define B_  4
#define T_  4096
#define D_  1024
#define R_  128
#define DFF_ 4096
#define BT_ (B_ * T_)   // 16384

// ---------------------------------------------------------------------------
// Scratch (device globals; allocation-free)
// ---------------------------------------------------------------------------
__device__ __half g_normed[(size_t)BT_ * D_];   // 32 MB
__device__ float  g_q[(size_t)BT_ * R_];
__device__ float  g_k[(size_t)BT_ * R_];
__device__ float  g_v[(size_t)BT_ * R_];
__device__ __half g_y[(size_t)BT_ * R_];
__device__ __half g_h[(size_t)BT_ * D_];        // 32 MB
__device__ float  g_t1[(size_t)BT_ * DFF_];     // 256 MB
__device__ __half g_t1h[(size_t)BT_ * DFF_];    // 128 MB
// fp16 weights
__device__ __half g_wq[(size_t)R_ * D_];
__device__ __half g_wk[(size_t)R_ * D_];
__device__ __half g_wv[(size_t)R_ * D_];
__device__ __half g_wo[(size_t)D_ * R_];
__device__ __half g_w1[(size_t)DFF_ * D_];
__device__ __half g_w3[(size_t)DFF_ * D_];
__device__ __half g_w2[(size_t)D_ * DFF_];

// ---------------------------------------------------------------------------
// Helpers
// ---------------------------------------------------------------------------
__device__ __forceinline__ void mma_f16(float& c0, float& c1, float& c2, float& c3,
                                        uint32_t a0, uint32_t a1, uint32_t a2, uint32_t a3,
                                        uint32_t b0, uint32_t b1) {
    asm volatile(
        "mma.sync.aligned.m16n8k16.row.col.f32.f16.f16.f32 "
        "{%0,%1,%2,%3}, {%4,%5,%6,%7}, {%8,%9}, {%0,%1,%2,%3};\n"
        : "+f"(c0), "+f"(c1), "+f"(c2), "+f"(c3)
        : "r"(a0), "r"(a1), "r"(a2), "r"(a3), "r"(b0), "r"(b1));
}

__device__ __forceinline__ void cp_async16(void* smem, const void* gmem) {
    uint32_t s = (uint32_t)__cvta_generic_to_shared(smem);
    asm volatile("cp.async.ca.shared.global [%0], [%1], 16;\n" :: "r"(s), "l"(gmem));
}
__device__ __forceinline__ void cp_commit() { asm volatile("cp.async.commit_group;\n" ::: "memory"); }
__device__ __forceinline__ void cp_wait0()  { asm volatile("cp.async.wait_group 0;\n" ::: "memory"); }
__device__ __forceinline__ void cp_wait1()  { asm volatile("cp.async.wait_group 1;\n" ::: "memory"); }

// ---------------------------------------------------------------------------
// fp32 -> fp16 weight conversion
// ---------------------------------------------------------------------------
__global__ void __launch_bounds__(256) tohalf_kernel(const float4* __restrict__ in,
                                                     __half2* __restrict__ out, int n4) {
    int i = blockIdx.x * 256 + threadIdx.x;
    if (i < n4) {
        float4 v = in[i];
        out[2 * i]     = __floats2half2_rn(v.x, v.y);
        out[2 * i + 1] = __floats2half2_rn(v.z, v.w);
    }
}

// ---------------------------------------------------------------------------
// RMSNorm: one block per row of D_=1024; fp16 output (GEMM A operand)
// ---------------------------------------------------------------------------
__global__ void __launch_bounds__(256) rmsnorm_kernel(const float* __restrict__ x,
                                                      const float* __restrict__ w,
                                                      __half* __restrict__ out) {
    const size_t row = blockIdx.x;
    const float* xr = x + row * D_;
    float s = 0.f;
    for (int i = threadIdx.x; i < D_; i += 256) {
        float v = xr[i];
        s += v * v;
    }
    __shared__ float red[256];
    red[threadIdx.x] = s;
    __syncthreads();
    for (int off = 128; off > 0; off >>= 1) {
        if (threadIdx.x < off) red[threadIdx.x] += red[threadIdx.x + off];
        __syncthreads();
    }
    const float rms = rsqrtf(red[0] / (float)D_ + 1e-6f);
    __half* orow = out + row * D_;
    for (int i = threadIdx.x; i < D_; i += 256) {
        orow[i] = __float2half_rn(xr[i] * rms * w[i]);
    }
}

// ---------------------------------------------------------------------------
// FP16 tensor-core GEMM: C[M,N] = A[M,K] @ B[N,K]^T  (+ epilogue)
//   MODE 0: C = acc                         (fp32)
//   MODE 1: C = X + acc                     (fp32 residual; X may alias C)
//   MODE 2: Ch = half(X * silu(acc))        (FFN gate -> fp16 output)
// CTA 128x128, warp tile 64x32 (8 warps 2x4), BK=32, 2-stage cp.async
// (prefetch distance 2). Smem tiles [128][40] halves (80B row = 20 banks:
// fragment rows hit all 32 banks, conflict-free). Dynamic smem 40KB.
// Requires M%128==0, N%128==0, K%32==0.
// ---------------------------------------------------------------------------
#define HPAD 40
#define HTILE (128 * HPAD)                       // halves per tile per stage
#define GEMM_SMEM_BYTES (4 * HTILE * 2)          // 2 bufs x (A+B) = 40960 B

template <int MODE>
__device__ __forceinline__ void run_hgemm(const __half* __restrict__ A,
                                          const __half* __restrict__ Bm,
                                          const float* __restrict__ X,
                                          float* __restrict__ C,
                                          __half* __restrict__ Ch,
                                          int M, int N, int K, int bm, int bn) {
    extern __shared__ __align__(16) __half hsm[];
    __half* AsBase = hsm;                    // [2][128][HPAD]
    __half* BsBase = hsm + 2 * HTILE;        // [2][128][HPAD]

    const int tid  = threadIdx.x;
    const int lane = tid & 31;
    const int wid  = tid >> 5;
    const int wr   = (wid >> 2) * 64;   // warp row base: 0 or 64
    const int wc   = (wid & 3) * 32;    // warp col base: 0,32,64,96
    const int gm   = lane >> 2;         // 0..7
    const int kq   = lane & 3;          // 0..3
    const int q2   = kq * 2;

    // loaders: row = tid>>1 (0..127), half-offset 0 or 16; 2x cp.async16 each matrix
    const int lrow = tid >> 1;
    const int lc   = (tid & 1) * 16;

    const __half* Aptr = A + (size_t)(bm + lrow) * K + lc;
    const __half* Bptr = Bm + (size_t)(bn + lrow) * K + lc;

    float acc[4][4][4];
#pragma unroll
    for (int mi = 0; mi < 4; mi++)
#pragma unroll
        for (int ni = 0; ni < 4; ni++)
#pragma unroll
            for (int r = 0; r < 4; r++) acc[mi][ni][r] = 0.f;

    auto load_stage = [&](int buf, int k0) {
        __half* As = AsBase + buf * HTILE;
        __half* Bs = BsBase + buf * HTILE;
        cp_async16(&As[lrow * HPAD + lc], Aptr + k0);
        cp_async16(&As[lrow * HPAD + lc + 8], Aptr + k0 + 8);
        cp_async16(&Bs[lrow * HPAD + lc], Bptr + k0);
        cp_async16(&Bs[lrow * HPAD + lc + 8], Bptr + k0 + 8);
        cp_commit();
    };

    const int NT = K >> 5;
    load_stage(0, 0);
    if (NT > 1) load_stage(1, 32);

    for (int it = 0; it < NT; it++) {
        if (it + 1 < NT) cp_wait1(); else cp_wait0();
        __syncthreads();

        const int buf = it & 1;
        const __half* As = AsBase + buf * HTILE;
        const __half* Bs = BsBase + buf * HTILE;

#pragma unroll
        for (int ks = 0; ks < 2; ks++) {
            const int kb = ks * 16;
            uint32_t af[4][4], bf[4][2];
#pragma unroll
            for (int mi = 0; mi < 4; mi++) {
                const __half* ap = As + (wr + mi * 16 + gm) * HPAD + kb + q2;
                af[mi][0] = *(const uint32_t*)(ap);
                af[mi][1] = *(const uint32_t*)(ap + 8 * HPAD);
                af[mi][2] = *(const uint32_t*)(ap + 8);
                af[mi][3] = *(const uint32_t*)(ap + 8 * HPAD + 8);
            }
#pragma unroll
            for (int ni = 0; ni < 4; ni++) {
                const __half* bp = Bs + (wc + ni * 8 + gm) * HPAD + kb + q2;
                bf[ni][0] = *(const uint32_t*)(bp);
                bf[ni][1] = *(const uint32_t*)(bp + 8);
            }
#pragma unroll
            for (int mi = 0; mi < 4; mi++)
#pragma unroll
                for (int ni = 0; ni < 4; ni++)
                    mma_f16(acc[mi][ni][0], acc[mi][ni][1], acc[mi][ni][2], acc[mi][ni][3],
                            af[mi][0], af[mi][1], af[mi][2], af[mi][3],
                            bf[ni][0], bf[ni][1]);
        }
        __syncthreads();
        if (it + 2 < NT) load_stage(buf, (it + 2) * 32);
    }

    // epilogue: c0,c1 -> (row gm, cols 2kq,2kq+1); c2,c3 -> row gm+8
#pragma unroll
    for (int mi = 0; mi < 4; mi++) {
        const int r0 = bm + wr + mi * 16 + gm;
        const int r1 = r0 + 8;
#pragma unroll
        for (int ni = 0; ni < 4; ni++) {
            const int c = bn + wc + ni * 8 + q2;
            const size_t o0 = (size_t)r0 * N + c;
            const size_t o1 = (size_t)r1 * N + c;
            float2 v0 = make_float2(acc[mi][ni][0], acc[mi][ni][1]);
            float2 v1 = make_float2(acc[mi][ni][2], acc[mi][ni][3]);
            if (MODE == 0) {
                *(float2*)(&C[o0]) = v0;
                *(float2*)(&C[o1]) = v1;
            } else if (MODE == 1) {
                float2 x0 = *(const float2*)(&X[o0]);
                float2 x1 = *(const float2*)(&X[o1]);
                v0.x += x0.x; v0.y += x0.y;
                v1.x += x1.x; v1.y += x1.y;
                *(float2*)(&C[o0]) = v0;
                *(float2*)(&C[o1]) = v1;
            } else {
                float2 x0 = *(const float2*)(&X[o0]);
                float2 x1 = *(const float2*)(&X[o1]);
                float g0 = x0.x * (v0.x / (1.f + expf(-v0.x)));
                float g1 = x0.y * (v0.y / (1.f + expf(-v0.y)));
                float g2 = x1.x * (v1.x / (1.f + expf(-v1.x)));
                float g3 = x1.y * (v1.y / (1.f + expf(-v1.y)));
                *(__half2*)(&Ch[o0]) = __floats2half2_rn(g0, g1);
                *(__half2*)(&Ch[o1]) = __floats2half2_rn(g2, g3);
            }
        }
    }
}

template <int MODE>
__global__ void __launch_bounds__(256, 2) hgemm_kernel(const __half* __restrict__ A,
                                                       const __half* __restrict__ Bm,
                                                       const float* __restrict__ X,
                                                       float* __restrict__ C,
                                                       __half* __restrict__ Ch,
                                                       int M, int N, int K) {
    run_hgemm<MODE>(A, Bm, X, C, Ch, M, N, K, blockIdx.y * 128, blockIdx.x * 128);
}

// Fused QKV: grid (3, M/128); blockIdx.x selects weight/output
__global__ void __launch_bounds__(256, 2) qkv_kernel(const __half* __restrict__ A,
                                                     const __half* __restrict__ Bq,
                                                     const __half* __restrict__ Bk,
                                                     const __half* __restrict__ Bv,
                                                     float* __restrict__ Cq,
                                                     float* __restrict__ Ck,
                                                     float* __restrict__ Cv,
                                                     int M, int K) {
    const __half* Bm = (blockIdx.x == 0) ? Bq : (blockIdx.x == 1) ? Bk : Bv;
    float* C = (blockIdx.x == 0) ? Cq : (blockIdx.x == 1) ? Ck : Cv;
    run_hgemm<0>(A, Bm, nullptr, C, nullptr, M, R_, K, blockIdx.y * 128, 0);
}

// ---------------------------------------------------------------------------
// RoPE (in-place on q and k)
// ---------------------------------------------------------------------------
__global__ void __launch_bounds__(64) rope_kernel(float* __restrict__ q,
                                                  float* __restrict__ k,
                                                  const float* __restrict__ cosp,
                                                  const float* __restrict__ sinp) {
    const int bt = blockIdx.x;
    const int j = threadIdx.x;
    const int t = bt & (T_ - 1);
    const float c = cosp[t * 64 + j];
    const float s = sinp[t * 64 + j];
    const size_t base = (size_t)bt * R_;

    float q1 = q[base + j], q2 = q[base + 64 + j];
    q[base + j]      = q1 * c + q2 * s;
    q[base + 64 + j] = q2 * c - q1 * s;

    float k1 = k[base + j], k2 = k[base + 64 + j];
    k[base + j]      = k1 * c + k2 * s;
    k[base + 64 + j] = k2 * c - k1 * s;
}

// ---------------------------------------------------------------------------
// Sliding-window causal attention, flash-style online softmax.
// Output y in fp16 (A operand of Wo GEMM).
// ---------------------------------------------------------------------------
#define ATTN_SMEM_FLOATS (32 * 128 + 32 * 128 + 64 * 132)
#define ATTN_SMEM_BYTES (ATTN_SMEM_FLOATS * 4)

__global__ void __launch_bounds__(64) attn_kernel(const float* __restrict__ q,
                                                  const float* __restrict__ k,
                                                  const float* __restrict__ v,
                                                  __half* __restrict__ y,
                                                  const int* __restrict__ win_ptr) {
    extern __shared__ float sm[];
    float* k_s = sm;
    float* v_s = k_s + 32 * 128;
    float* O_s = v_s + 32 * 128;

    const int b = blockIdx.y;
    const int t0 = blockIdx.x * 64;
    const int tid = threadIdx.x;
    const int W = win_ptr[0];
    const float scale = rsqrtf((float)R_);
    const size_t qbase = ((size_t)b * T_ + t0) * R_;

    float4 qr[32];
    {
        const float4* qp = (const float4*)(q + qbase + (size_t)tid * R_);
#pragma unroll
        for (int i = 0; i < 32; i++) {
            float4 t = qp[i];
            qr[i] = make_float4(t.x * scale, t.y * scale, t.z * scale, t.w * scale);
        }
    }
    {
        float4 z = make_float4(0.f, 0.f, 0.f, 0.f);
        float4* Or4 = (float4*)(O_s + tid * 132);
#pragma unroll
        for (int d4 = 0; d4 < 32; d4++) Or4[d4] = z;
    }
    __syncthreads();

    const int t = t0 + tid;
    float m = -1e30f, l = 0.f;

    int s_lo = t0 - W;
    if (s_lo < 0) s_lo = 0;
    const int s_start = s_lo & ~31;

    for (int s0 = s_start; s0 < t0 + 64; s0 += 32) {
        {
            const float4* kp = (const float4*)(k + ((size_t)b * T_ + s0) * R_);
            const float4* vp = (const float4*)(v + ((size_t)b * T_ + s0) * R_);
            float4* ks4 = (float4*)k_s;
            float4* vs4 = (float4*)v_s;
#pragma unroll
            for (int i = 0; i < 16; i++) {
                ks4[tid + i * 64] = kp[tid + i * 64];
                vs4[tid + i * 64] = vp[tid + i * 64];
            }
        }
        __syncthreads();

        float p[32];
        float mt = m;
#pragma unroll 4
        for (int j = 0; j < 32; j++) {
            const float4* kr = (const float4*)(k_s + j * 128);
            float4 s4 = make_float4(0.f, 0.f, 0.f, 0.f);
#pragma unroll
            for (int d4 = 0; d4 < 32; d4++) {
                float4 kv = kr[d4];
                s4.x += qr[d4].x * kv.x;
                s4.y += qr[d4].y * kv.y;
                s4.z += qr[d4].z * kv.z;
                s4.w += qr[d4].w * kv.w;
            }
            float s = (s4.x + s4.y) + (s4.z + s4.w);
            const int sidx = s0 + j;
            if (sidx > t || (t - sidx) > W) s = -1e30f;
            p[j] = s;
            mt = fmaxf(mt, s);
        }

        const float alpha = expf(m - mt);
        m = mt;
        float lt = 0.f;
#pragma unroll
        for (int j = 0; j < 32; j++) {
            const float pv = (p[j] > -1e29f) ? expf(p[j] - mt) : 0.f;
            p[j] = pv;
            lt += pv;
        }
        l = l * alpha + lt;

        float4* Or4 = (float4*)(O_s + tid * 132);
        const float4* vs4 = (const float4*)v_s;
#pragma unroll 2
        for (int d4 = 0; d4 < 32; d4++) {
            float4 acc = Or4[d4];
            acc.x *= alpha; acc.y *= alpha; acc.z *= alpha; acc.w *= alpha;
#pragma unroll
            for (int j = 0; j < 32; j++) {
                float4 vv = vs4[j * 32 + d4];
                acc.x += p[j] * vv.x;
                acc.y += p[j] * vv.y;
                acc.z += p[j] * vv.z;
                acc.w += p[j] * vv.w;
            }
            Or4[d4] = acc;
        }
        __syncthreads();
    }

    const float inv_l = 1.f / l;
    __half2* yo = (__half2*)(y + qbase + (size_t)tid * R_);
    const float4* Or4 = (const float4*)(O_s + tid * 132);
#pragma unroll
    for (int d4 = 0; d4 < 32; d4++) {
        float4 o = Or4[d4];
        yo[2 * d4]     = __floats2half2_rn(o.x * inv_l, o.y * inv_l);
        yo[2 * d4 + 1] = __floats2half2_rn(o.z * inv_l, o.w * inv_l);
    }
}

// ---------------------------------------------------------------------------
// Host launcher
// ---------------------------------------------------------------------------
extern "C" void kernel_launch(void* const* d_in, const int* in_sizes, int n_in,
                              void* d_out, int out_size) {
    const float* x    = (const float*)d_in[0];
    const float* Uq   = (const float*)d_in[1];
    const float* Uk   = (const float*)d_in[2];
    const float* Uv   = (const float*)d_in[3];
    const float* cosp = (const float*)d_in[4];
    const float* sinp = (const float*)d_in[5];
    const float* ln1w = (const float*)d_in[6];
    const float* ln2w = (const float*)d_in[7];
    const float* Wo   = (const float*)d_in[8];
    const float* w1   = (const float*)d_in[9];
    const float* w3   = (const float*)d_in[10];
    const float* w2   = (const float*)d_in[11];
    const int*   win  = (const int*)d_in[12];
    float* out = (float*)d_out;

    __half *normed, *y, *h, *t1h;
    float *q, *k, *v, *t1;
    __half *wq, *wk, *wv, *wo, *w1h, *w3h, *w2h;
    cudaGetSymbolAddress((void**)&normed, g_normed);
    cudaGetSymbolAddress((void**)&q, g_q);
    cudaGetSymbolAddress((void**)&k, g_k);
    cudaGetSymbolAddress((void**)&v, g_v);
    cudaGetSymbolAddress((void**)&y, g_y);
    cudaGetSymbolAddress((void**)&h, g_h);
    cudaGetSymbolAddress((void**)&t1, g_t1);
    cudaGetSymbolAddress((void**)&t1h, g_t1h);
    cudaGetSymbolAddress((void**)&wq, g_wq);
    cudaGetSymbolAddress((void**)&wk, g_wk);
    cudaGetSymbolAddress((void**)&wv, g_wv);
    cudaGetSymbolAddress((void**)&wo, g_wo);
    cudaGetSymbolAddress((void**)&w1h, g_w1);
    cudaGetSymbolAddress((void**)&w3h, g_w3);
    cudaGetSymbolAddress((void**)&w2h, g_w2);

    cudaFuncSetAttribute(attn_kernel, cudaFuncAttributeMaxDynamicSharedMemorySize,
                         ATTN_SMEM_BYTES);

    // weight prep (fp16 conversion)
    const int nSmall = R_ * D_ / 4;
    const int nBig   = DFF_ * D_ / 4;
    tohalf_kernel<<<(nSmall + 255) / 256, 256>>>((const float4*)Uq, (__half2*)wq, nSmall);
    tohalf_kernel<<<(nSmall + 255) / 256, 256>>>((const float4*)Uk, (__half2*)wk, nSmall);
    tohalf_kernel<<<(nSmall + 255) / 256, 256>>>((const float4*)Uv, (__half2*)wv, nSmall);
    tohalf_kernel<<<(nSmall + 255) / 256, 256>>>((const float4*)Wo, (__half2*)wo, nSmall);
    tohalf_kernel<<<(nBig + 255) / 256, 256>>>((const float4*)w1, (__half2*)w1h, nBig);
    tohalf_kernel<<<(nBig + 255) / 256, 256>>>((const float4*)w3, (__half2*)w3h, nBig);
    tohalf_kernel<<<(nBig + 255) / 256, 256>>>((const float4*)w2, (__half2*)w2h, nBig);

    // 1) normed = fp16(rmsnorm(x, ln1_w))
    rmsnorm_kernel<<<BT_, 256>>>(x, ln1w, normed);

    // 2) fused q,k,v projections (fp32 out)
    qkv_kernel<<<dim3(3, BT_ / 128), 256, GEMM_SMEM_BYTES>>>(normed, wq, wk, wv, q, k, v, BT_, D_);

    // 3) RoPE
    rope_kernel<<<BT_, 64>>>(q, k, cosp, sinp);

    // 4) attention -> y (fp16)
    attn_kernel<<<dim3(T_ / 64, B_), 64, ATTN_SMEM_BYTES>>>(q, k, v, y, win);

    // 5) out = x + y @ Wo^T
    hgemm_kernel<1><<<dim3(D_ / 128, BT_ / 128), 256, GEMM_SMEM_BYTES>>>(
        y, wo, x, out, nullptr, BT_, D_, R_);

    // 6) h = fp16(rmsnorm(out, ln2_w))
    rmsnorm_kernel<<<BT_, 256>>>(out, ln2w, h);

    // 7) t1 = h @ w1^T  (fp32 out)
    hgemm_kernel<0><<<dim3(DFF_ / 128, BT_ / 128), 256, GEMM_SMEM_BYTES>>>(
        h, w1h, nullptr, t1, nullptr, BT_, DFF_, D_);

    // 8) t1h = fp16(t1 * silu(h @ w3^T))
    hgemm_kernel<2><<<dim3(DFF_ / 128, BT_ / 128), 256, GEMM_SMEM_BYTES>>>(
        h, w3h, t1, nullptr, t1h, BT_, DFF_, D_);

    // 9) out = out + t1h @ w2^T
    hgemm_kernel<1><<<dim3(D_ / 128, BT_ / 128), 256, GEMM_SMEM_BYTES>>>(
        t1h, w2h, out, out, nullptr, BT_, D_, DFF_);
}

// round 10
// speedup vs baseline: 1.2747x; 1.2747x over previous
#include <cuda_runtime.h>
#include <cuda_fp16.h>
#include <math.h>
#include <stdint.h>

// Problem dims (fixed by the dataset)
#define B_  4
#define T_  4096
#define D_  1024
#define R_  128
#define DFF_ 4096
#define BT_ (B_ * T_)   // 16384

typedef unsigned long long ULL;

// ---------------------------------------------------------------------------
// Scratch (device globals; allocation-free)
// ---------------------------------------------------------------------------
__device__ float g_normed[(size_t)BT_ * D_];   // 64 MB
__device__ float g_q[(size_t)BT_ * R_];
__device__ float g_k[(size_t)BT_ * R_];
__device__ float g_v[(size_t)BT_ * R_];
__device__ float g_y[(size_t)BT_ * R_];
__device__ float g_h[(size_t)BT_ * D_];        // 64 MB
__device__ float g_t1[(size_t)BT_ * DFF_];     // 256 MB
// tf32-rounded weights
__device__ float g_wq[(size_t)R_ * D_];
__device__ float g_wk[(size_t)R_ * D_];
__device__ float g_wv[(size_t)R_ * D_];
__device__ float g_wo[(size_t)D_ * R_];
__device__ float g_w1[(size_t)DFF_ * D_];
__device__ float g_w3[(size_t)DFF_ * D_];
__device__ float g_w2[(size_t)D_ * DFF_];

// ---------------------------------------------------------------------------
// Helpers
// ---------------------------------------------------------------------------
__device__ __forceinline__ uint32_t tf32_bits(float x) {
    uint32_t u;
    asm("cvt.rna.tf32.f32 %0, %1;" : "=r"(u) : "f"(x));
    return u;
}
__device__ __forceinline__ float tf32f(float x) { return __uint_as_float(tf32_bits(x)); }

__device__ __forceinline__ void mma_tf32(float& c0, float& c1, float& c2, float& c3,
                                         uint32_t a0, uint32_t a1, uint32_t a2, uint32_t a3,
                                         uint32_t b0, uint32_t b1) {
    asm volatile(
        "mma.sync.aligned.m16n8k8.row.col.f32.tf32.tf32.f32 "
        "{%0,%1,%2,%3}, {%4,%5,%6,%7}, {%8,%9}, {%0,%1,%2,%3};\n"
        : "+f"(c0), "+f"(c1), "+f"(c2), "+f"(c3)
        : "r"(a0), "r"(a1), "r"(a2), "r"(a3), "r"(b0), "r"(b1));
}

__device__ __forceinline__ void cp_async16(void* smem, const void* gmem) {
    uint32_t s = (uint32_t)__cvta_generic_to_shared(smem);
    asm volatile("cp.async.ca.shared.global [%0], [%1], 16;\n" :: "r"(s), "l"(gmem));
}
__device__ __forceinline__ void cp_commit() { asm volatile("cp.async.commit_group;\n" ::: "memory"); }
__device__ __forceinline__ void cp_wait0()  { asm volatile("cp.async.wait_group 0;\n" ::: "memory"); }
__device__ __forceinline__ void cp_wait1()  { asm volatile("cp.async.wait_group 1;\n" ::: "memory"); }

// Packed f32x2 (Blackwell FFMA2 path)
#define FMA2(d, a, b, c) \
    asm("fma.rn.f32x2 %0, %1, %2, %3;" : "=l"(d) : "l"(a), "l"(b), "l"(c))
#define MUL2(d, a, b) \
    asm("mul.rn.f32x2 %0, %1, %2;" : "=l"(d) : "l"(a), "l"(b))

__device__ __forceinline__ ULL pk2(float lo, float hi) {
    ULL d;
    asm("mov.b64 %0, {%1,%2};" : "=l"(d)
        : "r"(__float_as_uint(lo)), "r"(__float_as_uint(hi)));
    return d;
}
__device__ __forceinline__ float2 upk2(ULL v) {
    uint32_t lo, hi;
    asm("mov.b64 {%0,%1}, %2;" : "=r"(lo), "=r"(hi) : "l"(v));
    return make_float2(__uint_as_float(lo), __uint_as_float(hi));
}

// ---------------------------------------------------------------------------
// Fused tf32 rounding prep for ALL weights (one launch)
// ---------------------------------------------------------------------------
#define NS_ (R_ * D_ / 4)      // 32768 float4 per small weight
#define NB_ (DFF_ * D_ / 4)    // 1048576 float4 per big weight
#define PREP_TOTAL (4 * NS_ + 3 * NB_)   // 3276800

__global__ void __launch_bounds__(256) prep_kernel(
    const float4* __restrict__ Uq, const float4* __restrict__ Uk,
    const float4* __restrict__ Uv, const float4* __restrict__ Wo,
    const float4* __restrict__ w1, const float4* __restrict__ w3,
    const float4* __restrict__ w2,
    float4* __restrict__ oq, float4* __restrict__ ok,
    float4* __restrict__ ov, float4* __restrict__ oo,
    float4* __restrict__ o1, float4* __restrict__ o3, float4* __restrict__ o2) {
    int i = blockIdx.x * 256 + threadIdx.x;
    const float4* src;
    float4* dst;
    int off;
    if (i < 4 * NS_) {
        int seg = i >> 15;           // /NS_
        off = i & (NS_ - 1);
        src = (seg == 0) ? Uq : (seg == 1) ? Uk : (seg == 2) ? Uv : Wo;
        dst = (seg == 0) ? oq : (seg == 1) ? ok : (seg == 2) ? ov : oo;
    } else {
        int j = i - 4 * NS_;
        int seg = j >> 20;           // /NB_
        off = j & (NB_ - 1);
        src = (seg == 0) ? w1 : (seg == 1) ? w3 : w2;
        dst = (seg == 0) ? o1 : (seg == 1) ? o3 : o2;
    }
    float4 v = src[off];
    dst[off] = make_float4(tf32f(v.x), tf32f(v.y), tf32f(v.z), tf32f(v.w));
}

// ---------------------------------------------------------------------------
// RMSNorm: one block per row of D_=1024; output rounded to tf32
// ---------------------------------------------------------------------------
__global__ void __launch_bounds__(256) rmsnorm_kernel(const float* __restrict__ x,
                                                      const float* __restrict__ w,
                                                      float* __restrict__ out) {
    const size_t row = blockIdx.x;
    const float* xr = x + row * D_;
    float s = 0.f;
    for (int i = threadIdx.x; i < D_; i += 256) {
        float v = xr[i];
        s += v * v;
    }
    __shared__ float red[256];
    red[threadIdx.x] = s;
    __syncthreads();
    for (int off = 128; off > 0; off >>= 1) {
        if (threadIdx.x < off) red[threadIdx.x] += red[threadIdx.x + off];
        __syncthreads();
    }
    const float rms = rsqrtf(red[0] / (float)D_ + 1e-6f);
    float* orow = out + row * D_;
    for (int i = threadIdx.x; i < D_; i += 256) {
        orow[i] = tf32f(xr[i] * rms * w[i]);
    }
}

// ---------------------------------------------------------------------------
// TF32 tensor-core GEMM: C[M,N] = A[M,K] @ B[N,K]^T  (+ epilogue)
//   MODE 0: C = acc
//   MODE 1: C = X + acc
//   MODE 2: C = tf32(X * silu(acc))   (X may alias C)
// CTA 128x128, warp tile 64x32 (8 warps 2x4), BK=32, 2-stage cp.async
// (prefetch distance 2). Dynamic smem 73.7KB -> 2 CTAs/SM.
// ---------------------------------------------------------------------------
#define GP32 36
#define TILE_FLOATS (128 * GP32)
#define GEMM_SMEM_BYTES (4 * TILE_FLOATS * 4)   // 73728

template <int MODE>
__device__ __forceinline__ void run_gemm(const float* __restrict__ A,
                                         const float* __restrict__ Bm,
                                         const float* __restrict__ X,
                                         float* __restrict__ C,
                                         int M, int N, int K, int bm, int bn) {
    extern __shared__ __align__(16) float dsm[];
    float* AsBase = dsm;
    float* BsBase = dsm + 2 * TILE_FLOATS;

    const int tid  = threadIdx.x;
    const int lane = tid & 31;
    const int wid  = tid >> 5;
    const int wr   = (wid >> 2) * 64;
    const int wc   = (wid & 3) * 32;
    const int gm   = lane >> 2;
    const int kq   = lane & 3;

    const int cr  = tid >> 3;
    const int cc4 = (tid & 7) * 4;

    const float* Aptr = A + (size_t)(bm + cr) * K + cc4;
    const float* Bptr = Bm + (size_t)(bn + cr) * K + cc4;
    const size_t s32 = (size_t)32 * K;

    float acc[4][4][4];
#pragma unroll
    for (int mi = 0; mi < 4; mi++)
#pragma unroll
        for (int ni = 0; ni < 4; ni++)
#pragma unroll
            for (int r = 0; r < 4; r++) acc[mi][ni][r] = 0.f;

    auto load_stage = [&](int buf, int k0) {
        float* As = AsBase + buf * TILE_FLOATS;
        float* Bs = BsBase + buf * TILE_FLOATS;
#pragma unroll
        for (int p = 0; p < 4; p++) {
            cp_async16(&As[(cr + 32 * p) * GP32 + cc4], Aptr + k0 + p * s32);
            cp_async16(&Bs[(cr + 32 * p) * GP32 + cc4], Bptr + k0 + p * s32);
        }
        cp_commit();
    };

    const int NT = K >> 5;
    load_stage(0, 0);
    if (NT > 1) load_stage(1, 32);

    for (int it = 0; it < NT; it++) {
        if (it + 1 < NT) cp_wait1(); else cp_wait0();
        __syncthreads();

        const int buf = it & 1;
        const float* As = AsBase + buf * TILE_FLOATS;
        const float* Bs = BsBase + buf * TILE_FLOATS;

#pragma unroll
        for (int ks = 0; ks < 4; ks++) {
            const int kb = ks * 8;
            uint32_t af[4][4], bf[4][2];
#pragma unroll
            for (int mi = 0; mi < 4; mi++) {
                const int m0 = (wr + mi * 16 + gm) * GP32;
                af[mi][0] = __float_as_uint(As[m0 + kb + kq]);
                af[mi][1] = __float_as_uint(As[m0 + 8 * GP32 + kb + kq]);
                af[mi][2] = __float_as_uint(As[m0 + kb + kq + 4]);
                af[mi][3] = __float_as_uint(As[m0 + 8 * GP32 + kb + kq + 4]);
            }
#pragma unroll
            for (int ni = 0; ni < 4; ni++) {
                const int n0 = (wc + ni * 8 + gm) * GP32;
                bf[ni][0] = __float_as_uint(Bs[n0 + kb + kq]);
                bf[ni][1] = __float_as_uint(Bs[n0 + kb + kq + 4]);
            }
#pragma unroll
            for (int mi = 0; mi < 4; mi++)
#pragma unroll
                for (int ni = 0; ni < 4; ni++)
                    mma_tf32(acc[mi][ni][0], acc[mi][ni][1], acc[mi][ni][2], acc[mi][ni][3],
                             af[mi][0], af[mi][1], af[mi][2], af[mi][3],
                             bf[ni][0], bf[ni][1]);
        }
        __syncthreads();
        if (it + 2 < NT) load_stage(buf, (it + 2) * 32);
    }

    // epilogue
#pragma unroll
    for (int mi = 0; mi < 4; mi++) {
        const int r0 = bm + wr + mi * 16 + gm;
        const int r1 = r0 + 8;
#pragma unroll
        for (int ni = 0; ni < 4; ni++) {
            const int c = bn + wc + ni * 8 + 2 * kq;
            const size_t o0 = (size_t)r0 * N + c;
            const size_t o1 = (size_t)r1 * N + c;
            float2 v0 = make_float2(acc[mi][ni][0], acc[mi][ni][1]);
            float2 v1 = make_float2(acc[mi][ni][2], acc[mi][ni][3]);
            if (MODE == 1) {
                float2 x0 = *(const float2*)(&X[o0]);
                float2 x1 = *(const float2*)(&X[o1]);
                v0.x += x0.x; v0.y += x0.y;
                v1.x += x1.x; v1.y += x1.y;
            } else if (MODE == 2) {
                float2 x0 = *(const float2*)(&X[o0]);
                float2 x1 = *(const float2*)(&X[o1]);
                v0.x = tf32f(x0.x * __fdividef(v0.x, 1.f + __expf(-v0.x)));
                v0.y = tf32f(x0.y * __fdividef(v0.y, 1.f + __expf(-v0.y)));
                v1.x = tf32f(x1.x * __fdividef(v1.x, 1.f + __expf(-v1.x)));
                v1.y = tf32f(x1.y * __fdividef(v1.y, 1.f + __expf(-v1.y)));
            }
            *(float2*)(&C[o0]) = v0;
            *(float2*)(&C[o1]) = v1;
        }
    }
}

template <int MODE>
__global__ void __launch_bounds__(256, 2) tfgemm_kernel(const float* __restrict__ A,
                                                        const float* __restrict__ Bm,
                                                        const float* __restrict__ X,
                                                        float* __restrict__ C,
                                                        int M, int N, int K) {
    run_gemm<MODE>(A, Bm, X, C, M, N, K, blockIdx.y * 128, blockIdx.x * 128);
}

// Fused QKV: grid (3, M/128)
__global__ void __launch_bounds__(256, 2) qkv_kernel(const float* __restrict__ A,
                                                     const float* __restrict__ Bq,
                                                     const float* __restrict__ Bk,
                                                     const float* __restrict__ Bv,
                                                     float* __restrict__ Cq,
                                                     float* __restrict__ Ck,
                                                     float* __restrict__ Cv,
                                                     int M, int K) {
    const float* Bm = (blockIdx.x == 0) ? Bq : (blockIdx.x == 1) ? Bk : Bv;
    float* C = (blockIdx.x == 0) ? Cq : (blockIdx.x == 1) ? Ck : Cv;
    run_gemm<0>(A, Bm, nullptr, C, M, R_, K, blockIdx.y * 128, 0);
}

// ---------------------------------------------------------------------------
// RoPE (in-place on q and k)
// ---------------------------------------------------------------------------
__global__ void __launch_bounds__(64) rope_kernel(float* __restrict__ q,
                                                  float* __restrict__ k,
                                                  const float* __restrict__ cosp,
                                                  const float* __restrict__ sinp) {
    const int bt = blockIdx.x;
    const int j = threadIdx.x;
    const int t = bt & (T_ - 1);
    const float c = cosp[t * 64 + j];
    const float s = sinp[t * 64 + j];
    const size_t base = (size_t)bt * R_;

    float q1 = q[base + j], q2 = q[base + 64 + j];
    q[base + j]      = q1 * c + q2 * s;
    q[base + 64 + j] = q2 * c - q1 * s;

    float k1 = k[base + j], k2 = k[base + 64 + j];
    k[base + j]      = k1 * c + k2 * s;
    k[base + 64 + j] = k2 * c - k1 * s;
}

// ---------------------------------------------------------------------------
// Sliding-window causal attention, flash-style online softmax.
// Packed f32x2 FMA in score + PV loops. 64 queries/block, KV tile 32.
// ---------------------------------------------------------------------------
#define ATTN_SMEM_FLOATS (32 * 128 + 32 * 128 + 64 * 132)
#define ATTN_SMEM_BYTES (ATTN_SMEM_FLOATS * 4)

__global__ void __launch_bounds__(64) attn_kernel(const float* __restrict__ q,
                                                  const float* __restrict__ k,
                                                  const float* __restrict__ v,
                                                  float* __restrict__ y,
                                                  const int* __restrict__ win_ptr) {
    extern __shared__ float sm[];
    float* k_s = sm;                  // 32*128
    float* v_s = k_s + 32 * 128;      // 32*128
    float* O_s = v_s + 32 * 128;      // 64*132 (row stride 528B, 16B aligned)

    const int b = blockIdx.y;
    const int t0 = blockIdx.x * 64;
    const int tid = threadIdx.x;
    const int W = win_ptr[0];
    const float scale = rsqrtf((float)R_);
    const size_t qbase = ((size_t)b * T_ + t0) * R_;

    // q into packed registers (scaled): 64 b64 pairs
    ULL qr2[64];
    {
        const ulonglong2* qp = (const ulonglong2*)(q + qbase + (size_t)tid * R_);
        const ULL scale2 = pk2(scale, scale);
#pragma unroll
        for (int i2 = 0; i2 < 32; i2++) {
            ulonglong2 t = qp[i2];
            MUL2(qr2[2 * i2],     t.x, scale2);
            MUL2(qr2[2 * i2 + 1], t.y, scale2);
        }
    }
    // zero O
    {
        float4 z = make_float4(0.f, 0.f, 0.f, 0.f);
        float4* Or4 = (float4*)(O_s + tid * 132);
#pragma unroll
        for (int d4 = 0; d4 < 32; d4++) Or4[d4] = z;
    }
    __syncthreads();

    const int t = t0 + tid;
    float m = -1e30f, l = 0.f;

    int s_lo = t0 - W;
    if (s_lo < 0) s_lo = 0;
    const int s_start = s_lo & ~31;

    for (int s0 = s_start; s0 < t0 + 64; s0 += 32) {
        // load KV tile (coalesced float4)
        {
            const float4* kp = (const float4*)(k + ((size_t)b * T_ + s0) * R_);
            const float4* vp = (const float4*)(v + ((size_t)b * T_ + s0) * R_);
            float4* ks4 = (float4*)k_s;
            float4* vs4 = (float4*)v_s;
#pragma unroll
            for (int i = 0; i < 16; i++) {
                ks4[tid + i * 64] = kp[tid + i * 64];
                vs4[tid + i * 64] = vp[tid + i * 64];
            }
        }
        __syncthreads();

        // scores (packed dot products), raw s stored packed in p2
        ULL p2[32];
        float mt = m;
#pragma unroll 4
        for (int j = 0; j < 32; j++) {
            const ulonglong2* kr8 = (const ulonglong2*)(k_s + j * 128);
            ULL a0 = 0, a1 = 0, a2 = 0, a3 = 0;
#pragma unroll
            for (int i2 = 0; i2 < 32; i2 += 2) {
                ulonglong2 kv0 = kr8[i2];
                ulonglong2 kv1 = kr8[i2 + 1];
                FMA2(a0, qr2[2 * i2],     kv0.x, a0);
                FMA2(a1, qr2[2 * i2 + 1], kv0.y, a1);
                FMA2(a2, qr2[2 * i2 + 2], kv1.x, a2);
                FMA2(a3, qr2[2 * i2 + 3], kv1.y, a3);
            }
            float2 f0 = upk2(a0), f1 = upk2(a1), f2 = upk2(a2), f3 = upk2(a3);
            float s = ((f0.x + f0.y) + (f1.x + f1.y)) + ((f2.x + f2.y) + (f3.x + f3.y));
            const int sidx = s0 + j;
            if (sidx > t || (t - sidx) > W) s = -1e30f;
            p2[j] = pk2(s, s);
            mt = fmaxf(mt, s);
        }

        const float alpha = __expf(m - mt);
        m = mt;
        float lt = 0.f;
#pragma unroll
        for (int j = 0; j < 32; j++) {
            float sraw = upk2(p2[j]).x;
            float pv = (sraw > -1e29f) ? __expf(sraw - mt) : 0.f;
            lt += pv;
            p2[j] = pk2(pv, pv);
        }
        l = l * alpha + lt;

        // O = O*alpha + P V   (packed)
        {
            const ULL alpha2 = pk2(alpha, alpha);
            ulonglong2* Or8 = (ulonglong2*)(O_s + tid * 132);
            const ulonglong2* vs8 = (const ulonglong2*)v_s;
#pragma unroll 2
            for (int i2 = 0; i2 < 32; i2++) {
                ulonglong2 acc = Or8[i2];
                MUL2(acc.x, acc.x, alpha2);
                MUL2(acc.y, acc.y, alpha2);
#pragma unroll
                for (int j = 0; j < 32; j++) {
                    ulonglong2 vv = vs8[j * 32 + i2];
                    FMA2(acc.x, p2[j], vv.x, acc.x);
                    FMA2(acc.y, p2[j], vv.y, acc.y);
                }
                Or8[i2] = acc;
            }
        }
        __syncthreads();
    }

    const float inv_l = __fdividef(1.f, l);
    float4* yo = (float4*)(y + qbase + (size_t)tid * R_);
    const float4* Or4 = (const float4*)(O_s + tid * 132);
#pragma unroll
    for (int d4 = 0; d4 < 32; d4++) {
        float4 o = Or4[d4];
        yo[d4] = make_float4(tf32f(o.x * inv_l), tf32f(o.y * inv_l),
                             tf32f(o.z * inv_l), tf32f(o.w * inv_l));
    }
}

// ---------------------------------------------------------------------------
// Host launcher
// ---------------------------------------------------------------------------
extern "C" void kernel_launch(void* const* d_in, const int* in_sizes, int n_in,
                              void* d_out, int out_size) {
    const float* x    = (const float*)d_in[0];
    const float* Uq   = (const float*)d_in[1];
    const float* Uk   = (const float*)d_in[2];
    const float* Uv   = (const float*)d_in[3];
    const float* cosp = (const float*)d_in[4];
    const float* sinp = (const float*)d_in[5];
    const float* ln1w = (const float*)d_in[6];
    const float* ln2w = (const float*)d_in[7];
    const float* Wo   = (const float*)d_in[8];
    const float* w1   = (const float*)d_in[9];
    const float* w3   = (const float*)d_in[10];
    const float* w2   = (const float*)d_in[11];
    const int*   win  = (const int*)d_in[12];
    float* out = (float*)d_out;

    float *normed, *q, *k, *v, *y, *h, *t1;
    float *wq, *wk, *wv, *wo, *w1r, *w3r, *w2r;
    cudaGetSymbolAddress((void**)&normed, g_normed);
    cudaGetSymbolAddress((void**)&q, g_q);
    cudaGetSymbolAddress((void**)&k, g_k);
    cudaGetSymbolAddress((void**)&v, g_v);
    cudaGetSymbolAddress((void**)&y, g_y);
    cudaGetSymbolAddress((void**)&h, g_h);
    cudaGetSymbolAddress((void**)&t1, g_t1);
    cudaGetSymbolAddress((void**)&wq, g_wq);
    cudaGetSymbolAddress((void**)&wk, g_wk);
    cudaGetSymbolAddress((void**)&wv, g_wv);
    cudaGetSymbolAddress((void**)&wo, g_wo);
    cudaGetSymbolAddress((void**)&w1r, g_w1);
    cudaGetSymbolAddress((void**)&w3r, g_w3);
    cudaGetSymbolAddress((void**)&w2r, g_w2);

    cudaFuncSetAttribute(attn_kernel, cudaFuncAttributeMaxDynamicSharedMemorySize,
                         ATTN_SMEM_BYTES);
    cudaFuncSetAttribute(tfgemm_kernel<0>, cudaFuncAttributeMaxDynamicSharedMemorySize,
                         GEMM_SMEM_BYTES);
    cudaFuncSetAttribute(tfgemm_kernel<1>, cudaFuncAttributeMaxDynamicSharedMemorySize,
                         GEMM_SMEM_BYTES);
    cudaFuncSetAttribute(tfgemm_kernel<2>, cudaFuncAttributeMaxDynamicSharedMemorySize,
                         GEMM_SMEM_BYTES);
    cudaFuncSetAttribute(qkv_kernel, cudaFuncAttributeMaxDynamicSharedMemorySize,
                         GEMM_SMEM_BYTES);

    // launch 1: fused weight prep
    prep_kernel<<<PREP_TOTAL / 256, 256>>>(
        (const float4*)Uq, (const float4*)Uk, (const float4*)Uv, (const float4*)Wo,
        (const float4*)w1, (const float4*)w3, (const float4*)w2,
        (float4*)wq, (float4*)wk, (float4*)wv, (float4*)wo,
        (float4*)w1r, (float4*)w3r, (float4*)w2r);

    // launch 2: normed = tf32(rmsnorm(x, ln1_w))
    rmsnorm_kernel<<<BT_, 256>>>(x, ln1w, normed);

    // launch 3: fused q,k,v projections
    qkv_kernel<<<dim3(3, BT_ / 128), 256, GEMM_SMEM_BYTES>>>(normed, wq, wk, wv, q, k, v, BT_, D_);

    // launch 4: RoPE
    rope_kernel<<<BT_, 64>>>(q, k, cosp, sinp);

    // launch 5: attention -> y (tf32-rounded)
    attn_kernel<<<dim3(T_ / 64, B_), 64, ATTN_SMEM_BYTES>>>(q, k, v, y, win);

    // launch 6 (ncu target): out = x + y @ Wo^T
    tfgemm_kernel<1><<<dim3(D_ / 128, BT_ / 128), 256, GEMM_SMEM_BYTES>>>(y, wo, x, out, BT_, D_, R_);

    // launch 7: h = tf32(rmsnorm(out, ln2_w))
    rmsnorm_kernel<<<BT_, 256>>>(out, ln2w, h);

    // launch 8: t1 = h @ w1^T
    tfgemm_kernel<0><<<dim3(DFF_ / 128, BT_ / 128), 256, GEMM_SMEM_BYTES>>>(h, w1r, nullptr, t1, BT_, DFF_, D_);

    // launch 9: t1 = tf32(t1 * silu(h @ w3^T))
    tfgemm_kernel<2><<<dim3(DFF_ / 128, BT_ / 128), 256, GEMM_SMEM_BYTES>>>(h, w3r, t1, t1, BT_, DFF_, D_);

    // launch 10: out = out + t1 @ w2^T
    tfgemm_kernel<1><<<dim3(D_ / 128, BT_ / 128), 256, GEMM_SMEM_BYTES>>>(t1, w2r, out, out, BT_, D_, DFF_);
}

// round 14
// speedup vs baseline: 1.2937x; 1.0149x over previous
#include <cuda_runtime.h>
#include <cuda_fp16.h>
#include <math.h>
#include <stdint.h>

// Problem dims (fixed by the dataset)
#define B_  4
#define T_  4096
#define D_  1024
#define R_  128
#define DFF_ 4096
#define BT_ (B_ * T_)   // 16384

typedef unsigned long long ULL;

// ---------------------------------------------------------------------------
// Scratch (device globals; allocation-free)
// ---------------------------------------------------------------------------
__device__ float g_normed[(size_t)BT_ * D_];   // 64 MB
__device__ float g_q[(size_t)BT_ * R_];
__device__ float g_k[(size_t)BT_ * R_];
__device__ float g_v[(size_t)BT_ * R_];
__device__ float g_y[(size_t)BT_ * R_];
__device__ float g_h[(size_t)BT_ * D_];        // 64 MB
__device__ float g_t1[(size_t)BT_ * DFF_];     // 256 MB
// tf32-rounded weights
__device__ float g_wq[(size_t)R_ * D_];
__device__ float g_wk[(size_t)R_ * D_];
__device__ float g_wv[(size_t)R_ * D_];
__device__ float g_wo[(size_t)D_ * R_];
__device__ float g_w1[(size_t)DFF_ * D_];
__device__ float g_w3[(size_t)DFF_ * D_];
__device__ float g_w2[(size_t)D_ * DFF_];

// ---------------------------------------------------------------------------
// Helpers
// ---------------------------------------------------------------------------
__device__ __forceinline__ uint32_t tf32_bits(float x) {
    uint32_t u;
    asm("cvt.rna.tf32.f32 %0, %1;" : "=r"(u) : "f"(x));
    return u;
}
__device__ __forceinline__ float tf32f(float x) { return __uint_as_float(tf32_bits(x)); }

__device__ __forceinline__ void mma_tf32(float& c0, float& c1, float& c2, float& c3,
                                         uint32_t a0, uint32_t a1, uint32_t a2, uint32_t a3,
                                         uint32_t b0, uint32_t b1) {
    asm volatile(
        "mma.sync.aligned.m16n8k8.row.col.f32.tf32.tf32.f32 "
        "{%0,%1,%2,%3}, {%4,%5,%6,%7}, {%8,%9}, {%0,%1,%2,%3};\n"
        : "+f"(c0), "+f"(c1), "+f"(c2), "+f"(c3)
        : "r"(a0), "r"(a1), "r"(a2), "r"(a3), "r"(b0), "r"(b1));
}

__device__ __forceinline__ void cp_async16(void* smem, const void* gmem) {
    uint32_t s = (uint32_t)__cvta_generic_to_shared(smem);
    asm volatile("cp.async.ca.shared.global [%0], [%1], 16;\n" :: "r"(s), "l"(gmem));
}
__device__ __forceinline__ void cp_commit() { asm volatile("cp.async.commit_group;\n" ::: "memory"); }
__device__ __forceinline__ void cp_wait0()  { asm volatile("cp.async.wait_group 0;\n" ::: "memory"); }
__device__ __forceinline__ void cp_wait1()  { asm volatile("cp.async.wait_group 1;\n" ::: "memory"); }

// Packed f32x2 (Blackwell FFMA2 path)
#define FMA2(d, a, b, c) \
    asm("fma.rn.f32x2 %0, %1, %2, %3;" : "=l"(d) : "l"(a), "l"(b), "l"(c))
#define MUL2(d, a, b) \
    asm("mul.rn.f32x2 %0, %1, %2;" : "=l"(d) : "l"(a), "l"(b))

__device__ __forceinline__ ULL pk2(float lo, float hi) {
    ULL d;
    asm("mov.b64 %0, {%1,%2};" : "=l"(d)
        : "r"(__float_as_uint(lo)), "r"(__float_as_uint(hi)));
    return d;
}
__device__ __forceinline__ float2 upk2(ULL v) {
    uint32_t lo, hi;
    asm("mov.b64 {%0,%1}, %2;" : "=r"(lo), "=r"(hi) : "l"(v));
    return make_float2(__uint_as_float(lo), __uint_as_float(hi));
}

// ---------------------------------------------------------------------------
// Fused tf32 rounding prep for ALL weights (one launch)
// ---------------------------------------------------------------------------
#define NS_ (R_ * D_ / 4)      // 32768 float4 per small weight
#define NB_ (DFF_ * D_ / 4)    // 1048576 float4 per big weight
#define PREP_TOTAL (4 * NS_ + 3 * NB_)   // 3276800

__global__ void __launch_bounds__(256) prep_kernel(
    const float4* __restrict__ Uq, const float4* __restrict__ Uk,
    const float4* __restrict__ Uv, const float4* __restrict__ Wo,
    const float4* __restrict__ w1, const float4* __restrict__ w3,
    const float4* __restrict__ w2,
    float4* __restrict__ oq, float4* __restrict__ ok,
    float4* __restrict__ ov, float4* __restrict__ oo,
    float4* __restrict__ o1, float4* __restrict__ o3, float4* __restrict__ o2) {
    int i = blockIdx.x * 256 + threadIdx.x;
    const float4* src;
    float4* dst;
    int off;
    if (i < 4 * NS_) {
        int seg = i >> 15;
        off = i & (NS_ - 1);
        src = (seg == 0) ? Uq : (seg == 1) ? Uk : (seg == 2) ? Uv : Wo;
        dst = (seg == 0) ? oq : (seg == 1) ? ok : (seg == 2) ? ov : oo;
    } else {
        int j = i - 4 * NS_;
        int seg = j >> 20;
        off = j & (NB_ - 1);
        src = (seg == 0) ? w1 : (seg == 1) ? w3 : w2;
        dst = (seg == 0) ? o1 : (seg == 1) ? o3 : o2;
    }
    float4 v = src[off];
    dst[off] = make_float4(tf32f(v.x), tf32f(v.y), tf32f(v.z), tf32f(v.w));
}

// ---------------------------------------------------------------------------
// RMSNorm: one block per row of D_=1024; output rounded to tf32
// ---------------------------------------------------------------------------
__global__ void __launch_bounds__(256) rmsnorm_kernel(const float* __restrict__ x,
                                                      const float* __restrict__ w,
                                                      float* __restrict__ out) {
    const size_t row = blockIdx.x;
    const float* xr = x + row * D_;
    float s = 0.f;
    for (int i = threadIdx.x; i < D_; i += 256) {
        float v = xr[i];
        s += v * v;
    }
    __shared__ float red[256];
    red[threadIdx.x] = s;
    __syncthreads();
    for (int off = 128; off > 0; off >>= 1) {
        if (threadIdx.x < off) red[threadIdx.x] += red[threadIdx.x + off];
        __syncthreads();
    }
    const float rms = rsqrtf(red[0] / (float)D_ + 1e-6f);
    float* orow = out + row * D_;
    for (int i = threadIdx.x; i < D_; i += 256) {
        orow[i] = tf32f(xr[i] * rms * w[i]);
    }
}

// ---------------------------------------------------------------------------
// Shared GEMM tile machinery: CTA 128x128 (or 128x[64+64] fused), warp tile
// 64x32, BK=32, 2-stage cp.async (prefetch distance 2). Smem 73.7KB.
// ---------------------------------------------------------------------------
#define GP32 36
#define TILE_FLOATS (128 * GP32)
#define GEMM_SMEM_BYTES (4 * TILE_FLOATS * 4)   // 73728

// ---------------------------------------------------------------------------
// Plain TF32 GEMM: C[M,N] = A[M,K] @ B[N,K]^T  (+ epilogue)
//   MODE 0: C = acc;  MODE 1: C = X + acc
// ---------------------------------------------------------------------------
template <int MODE>
__device__ __forceinline__ void run_gemm(const float* __restrict__ A,
                                         const float* __restrict__ Bm,
                                         const float* __restrict__ X,
                                         float* __restrict__ C,
                                         int M, int N, int K, int bm, int bn) {
    extern __shared__ __align__(16) float dsm[];
    float* AsBase = dsm;
    float* BsBase = dsm + 2 * TILE_FLOATS;

    const int tid  = threadIdx.x;
    const int lane = tid & 31;
    const int wid  = tid >> 5;
    const int wr   = (wid >> 2) * 64;
    const int wc   = (wid & 3) * 32;
    const int gm   = lane >> 2;
    const int kq   = lane & 3;

    const int cr  = tid >> 3;
    const int cc4 = (tid & 7) * 4;

    const float* Aptr = A + (size_t)(bm + cr) * K + cc4;
    const float* Bptr = Bm + (size_t)(bn + cr) * K + cc4;
    const size_t s32 = (size_t)32 * K;

    float acc[4][4][4];
#pragma unroll
    for (int mi = 0; mi < 4; mi++)
#pragma unroll
        for (int ni = 0; ni < 4; ni++)
#pragma unroll
            for (int r = 0; r < 4; r++) acc[mi][ni][r] = 0.f;

    auto load_stage = [&](int buf, int k0) {
        float* As = AsBase + buf * TILE_FLOATS;
        float* Bs = BsBase + buf * TILE_FLOATS;
#pragma unroll
        for (int p = 0; p < 4; p++) {
            cp_async16(&As[(cr + 32 * p) * GP32 + cc4], Aptr + k0 + p * s32);
            cp_async16(&Bs[(cr + 32 * p) * GP32 + cc4], Bptr + k0 + p * s32);
        }
        cp_commit();
    };

    const int NT = K >> 5;
    load_stage(0, 0);
    if (NT > 1) load_stage(1, 32);

    for (int it = 0; it < NT; it++) {
        if (it + 1 < NT) cp_wait1(); else cp_wait0();
        __syncthreads();

        const int buf = it & 1;
        const float* As = AsBase + buf * TILE_FLOATS;
        const float* Bs = BsBase + buf * TILE_FLOATS;

#pragma unroll
        for (int ks = 0; ks < 4; ks++) {
            const int kb = ks * 8;
            uint32_t af[4][4], bf[4][2];
#pragma unroll
            for (int mi = 0; mi < 4; mi++) {
                const int m0 = (wr + mi * 16 + gm) * GP32;
                af[mi][0] = __float_as_uint(As[m0 + kb + kq]);
                af[mi][1] = __float_as_uint(As[m0 + 8 * GP32 + kb + kq]);
                af[mi][2] = __float_as_uint(As[m0 + kb + kq + 4]);
                af[mi][3] = __float_as_uint(As[m0 + 8 * GP32 + kb + kq + 4]);
            }
#pragma unroll
            for (int ni = 0; ni < 4; ni++) {
                const int n0 = (wc + ni * 8 + gm) * GP32;
                bf[ni][0] = __float_as_uint(Bs[n0 + kb + kq]);
                bf[ni][1] = __float_as_uint(Bs[n0 + kb + kq + 4]);
            }
#pragma unroll
            for (int mi = 0; mi < 4; mi++)
#pragma unroll
                for (int ni = 0; ni < 4; ni++)
                    mma_tf32(acc[mi][ni][0], acc[mi][ni][1], acc[mi][ni][2], acc[mi][ni][3],
                             af[mi][0], af[mi][1], af[mi][2], af[mi][3],
                             bf[ni][0], bf[ni][1]);
        }
        __syncthreads();
        if (it + 2 < NT) load_stage(buf, (it + 2) * 32);
    }

#pragma unroll
    for (int mi = 0; mi < 4; mi++) {
        const int r0 = bm + wr + mi * 16 + gm;
        const int r1 = r0 + 8;
#pragma unroll
        for (int ni = 0; ni < 4; ni++) {
            const int c = bn + wc + ni * 8 + 2 * kq;
            const size_t o0 = (size_t)r0 * N + c;
            const size_t o1 = (size_t)r1 * N + c;
            float2 v0 = make_float2(acc[mi][ni][0], acc[mi][ni][1]);
            float2 v1 = make_float2(acc[mi][ni][2], acc[mi][ni][3]);
            if (MODE == 1) {
                float2 x0 = *(const float2*)(&X[o0]);
                float2 x1 = *(const float2*)(&X[o1]);
                v0.x += x0.x; v0.y += x0.y;
                v1.x += x1.x; v1.y += x1.y;
            }
            *(float2*)(&C[o0]) = v0;
            *(float2*)(&C[o1]) = v1;
        }
    }
}

template <int MODE>
__global__ void __launch_bounds__(256, 2) tfgemm_kernel(const float* __restrict__ A,
                                                        const float* __restrict__ Bm,
                                                        const float* __restrict__ X,
                                                        float* __restrict__ C,
                                                        int M, int N, int K) {
    run_gemm<MODE>(A, Bm, X, C, M, N, K, blockIdx.y * 128, blockIdx.x * 128);
}

// Fused QKV: grid (3, M/128)
__global__ void __launch_bounds__(256, 2) qkv_kernel(const float* __restrict__ A,
                                                     const float* __restrict__ Bq,
                                                     const float* __restrict__ Bk,
                                                     const float* __restrict__ Bv,
                                                     float* __restrict__ Cq,
                                                     float* __restrict__ Ck,
                                                     float* __restrict__ Cv,
                                                     int M, int K) {
    const float* Bm = (blockIdx.x == 0) ? Bq : (blockIdx.x == 1) ? Bk : Bv;
    float* C = (blockIdx.x == 0) ? Cq : (blockIdx.x == 1) ? Ck : Cv;
    run_gemm<0>(A, Bm, nullptr, C, M, R_, K, blockIdx.y * 128, 0);
}

// ---------------------------------------------------------------------------
// Fused FFN up+gate: C[M, bn..bn+64) = tf32( (A@w1^T) * silu(A@w3^T) )
// CTA output tile 128 x 64. Warps 0-3 compute u (w1), warps 4-7 compute g
// (w3), sharing the same A tiles. B smem rows 0-63 = w1, 64-127 = w3.
// Epilogue: u staged via smem U[128][UPAD] (UPAD=66 >= 64 cols — the R10
// build had UPAD=34 which aliased rows; fixed), g-warps gate + store.
// Eliminates the t1 fp32 round trip (512 MB DRAM).
// ---------------------------------------------------------------------------
#define UPAD 66   // >= 64 cols, even stride -> 8B-aligned float2

__global__ void __launch_bounds__(256, 2) ffn13_kernel(const float* __restrict__ A,
                                                       const float* __restrict__ B1,
                                                       const float* __restrict__ B3,
                                                       float* __restrict__ C,
                                                       int M, int N, int K) {
    extern __shared__ __align__(16) float dsm[];
    float* AsBase = dsm;
    float* BsBase = dsm + 2 * TILE_FLOATS;

    const int tid  = threadIdx.x;
    const int lane = tid & 31;
    const int wid  = tid >> 5;
    const int wsel = wid >> 2;               // 0 = u (w1), 1 = g (w3)
    const int wsub = wid & 3;
    const int wr   = (wsub >> 1) * 64;       // 0 or 64
    const int wc   = (wsub & 1) * 32;        // 0 or 32
    const int gm   = lane >> 2;
    const int kq   = lane & 3;

    const int bm = blockIdx.y * 128;
    const int bn = blockIdx.x * 64;          // 64 output cols per CTA

    const int cr  = tid >> 3;                // 0..31
    const int cc4 = (tid & 7) * 4;

    const float* Aptr  = A + (size_t)(bm + cr) * K + cc4;
    const float* B1ptr = B1 + (size_t)(bn + cr) * K + cc4;
    const float* B3ptr = B3 + (size_t)(bn + cr) * K + cc4;
    const size_t s32 = (size_t)32 * K;

    float acc[4][4][4];
#pragma unroll
    for (int mi = 0; mi < 4; mi++)
#pragma unroll
        for (int ni = 0; ni < 4; ni++)
#pragma unroll
            for (int r = 0; r < 4; r++) acc[mi][ni][r] = 0.f;

    auto load_stage = [&](int buf, int k0) {
        float* As = AsBase + buf * TILE_FLOATS;
        float* Bs = BsBase + buf * TILE_FLOATS;
#pragma unroll
        for (int p = 0; p < 4; p++)
            cp_async16(&As[(cr + 32 * p) * GP32 + cc4], Aptr + k0 + p * s32);
        cp_async16(&Bs[cr * GP32 + cc4],         B1ptr + k0);
        cp_async16(&Bs[(cr + 32) * GP32 + cc4],  B1ptr + k0 + s32);
        cp_async16(&Bs[(cr + 64) * GP32 + cc4],  B3ptr + k0);
        cp_async16(&Bs[(cr + 96) * GP32 + cc4],  B3ptr + k0 + s32);
        cp_commit();
    };

    const int NT = K >> 5;
    load_stage(0, 0);
    if (NT > 1) load_stage(1, 32);

    const int boff = wsel * 64;   // B smem row base for this warp group

    for (int it = 0; it < NT; it++) {
        if (it + 1 < NT) cp_wait1(); else cp_wait0();
        __syncthreads();

        const int buf = it & 1;
        const float* As = AsBase + buf * TILE_FLOATS;
        const float* Bs = BsBase + buf * TILE_FLOATS;

#pragma unroll
        for (int ks = 0; ks < 4; ks++) {
            const int kb = ks * 8;
            uint32_t af[4][4], bf[4][2];
#pragma unroll
            for (int mi = 0; mi < 4; mi++) {
                const int m0 = (wr + mi * 16 + gm) * GP32;
                af[mi][0] = __float_as_uint(As[m0 + kb + kq]);
                af[mi][1] = __float_as_uint(As[m0 + 8 * GP32 + kb + kq]);
                af[mi][2] = __float_as_uint(As[m0 + kb + kq + 4]);
                af[mi][3] = __float_as_uint(As[m0 + 8 * GP32 + kb + kq + 4]);
            }
#pragma unroll
            for (int ni = 0; ni < 4; ni++) {
                const int n0 = (boff + wc + ni * 8 + gm) * GP32;
                bf[ni][0] = __float_as_uint(Bs[n0 + kb + kq]);
                bf[ni][1] = __float_as_uint(Bs[n0 + kb + kq + 4]);
            }
#pragma unroll
            for (int mi = 0; mi < 4; mi++)
#pragma unroll
                for (int ni = 0; ni < 4; ni++)
                    mma_tf32(acc[mi][ni][0], acc[mi][ni][1], acc[mi][ni][2], acc[mi][ni][3],
                             af[mi][0], af[mi][1], af[mi][2], af[mi][3],
                             bf[ni][0], bf[ni][1]);
        }
        __syncthreads();
        if (it + 2 < NT) load_stage(buf, (it + 2) * 32);
    }

    // Epilogue: u warps stage to smem U[128][UPAD]; g warps gate + store.
    float* U = dsm;   // 128*66 = 8448 floats = 33.8KB, fits in idle stage mem
    if (wsel == 0) {
#pragma unroll
        for (int mi = 0; mi < 4; mi++) {
            const int r0 = (wr + mi * 16 + gm) * UPAD;
            const int r1 = r0 + 8 * UPAD;
#pragma unroll
            for (int ni = 0; ni < 4; ni++) {
                const int c = wc + ni * 8 + 2 * kq;
                *(float2*)(&U[r0 + c]) = make_float2(acc[mi][ni][0], acc[mi][ni][1]);
                *(float2*)(&U[r1 + c]) = make_float2(acc[mi][ni][2], acc[mi][ni][3]);
            }
        }
    }
    __syncthreads();
    if (wsel == 1) {
#pragma unroll
        for (int mi = 0; mi < 4; mi++) {
            const int lr0 = wr + mi * 16 + gm;
            const int lr1 = lr0 + 8;
#pragma unroll
            for (int ni = 0; ni < 4; ni++) {
                const int c = wc + ni * 8 + 2 * kq;
                float2 u0 = *(const float2*)(&U[lr0 * UPAD + c]);
                float2 u1 = *(const float2*)(&U[lr1 * UPAD + c]);
                float g0 = acc[mi][ni][0], g1 = acc[mi][ni][1];
                float g2 = acc[mi][ni][2], g3 = acc[mi][ni][3];
                float2 v0, v1;
                v0.x = tf32f(u0.x * __fdividef(g0, 1.f + __expf(-g0)));
                v0.y = tf32f(u0.y * __fdividef(g1, 1.f + __expf(-g1)));
                v1.x = tf32f(u1.x * __fdividef(g2, 1.f + __expf(-g2)));
                v1.y = tf32f(u1.y * __fdividef(g3, 1.f + __expf(-g3)));
                *(float2*)(&C[(size_t)(bm + lr0) * N + bn + c]) = v0;
                *(float2*)(&C[(size_t)(bm + lr1) * N + bn + c]) = v1;
            }
        }
    }
}

// ---------------------------------------------------------------------------
// RoPE (in-place on q and k)
// ---------------------------------------------------------------------------
__global__ void __launch_bounds__(64) rope_kernel(float* __restrict__ q,
                                                  float* __restrict__ k,
                                                  const float* __restrict__ cosp,
                                                  const float* __restrict__ sinp) {
    const int bt = blockIdx.x;
    const int j = threadIdx.x;
    const int t = bt & (T_ - 1);
    const float c = cosp[t * 64 + j];
    const float s = sinp[t * 64 + j];
    const size_t base = (size_t)bt * R_;

    float q1 = q[base + j], q2 = q[base + 64 + j];
    q[base + j]      = q1 * c + q2 * s;
    q[base + 64 + j] = q2 * c - q1 * s;

    float k1 = k[base + j], k2 = k[base + 64 + j];
    k[base + j]      = k1 * c + k2 * s;
    k[base + 64 + j] = k2 * c - k1 * s;
}

// ---------------------------------------------------------------------------
// Sliding-window causal attention, flash-style online softmax (FFMA2).
// ---------------------------------------------------------------------------
#define ATTN_SMEM_FLOATS (32 * 128 + 32 * 128 + 64 * 132)
#define ATTN_SMEM_BYTES (ATTN_SMEM_FLOATS * 4)

__global__ void __launch_bounds__(64) attn_kernel(const float* __restrict__ q,
                                                  const float* __restrict__ k,
                                                  const float* __restrict__ v,
                                                  float* __restrict__ y,
                                                  const int* __restrict__ win_ptr) {
    extern __shared__ float sm[];
    float* k_s = sm;
    float* v_s = k_s + 32 * 128;
    float* O_s = v_s + 32 * 128;

    const int b = blockIdx.y;
    const int t0 = blockIdx.x * 64;
    const int tid = threadIdx.x;
    const int W = win_ptr[0];
    const float scale = rsqrtf((float)R_);
    const size_t qbase = ((size_t)b * T_ + t0) * R_;

    ULL qr2[64];
    {
        const ulonglong2* qp = (const ulonglong2*)(q + qbase + (size_t)tid * R_);
        const ULL scale2 = pk2(scale, scale);
#pragma unroll
        for (int i2 = 0; i2 < 32; i2++) {
            ulonglong2 t = qp[i2];
            MUL2(qr2[2 * i2],     t.x, scale2);
            MUL2(qr2[2 * i2 + 1], t.y, scale2);
        }
    }
    {
        float4 z = make_float4(0.f, 0.f, 0.f, 0.f);
        float4* Or4 = (float4*)(O_s + tid * 132);
#pragma unroll
        for (int d4 = 0; d4 < 32; d4++) Or4[d4] = z;
    }
    __syncthreads();

    const int t = t0 + tid;
    float m = -1e30f, l = 0.f;

    int s_lo = t0 - W;
    if (s_lo < 0) s_lo = 0;
    const int s_start = s_lo & ~31;

    for (int s0 = s_start; s0 < t0 + 64; s0 += 32) {
        {
            const float4* kp = (const float4*)(k + ((size_t)b * T_ + s0) * R_);
            const float4* vp = (const float4*)(v + ((size_t)b * T_ + s0) * R_);
            float4* ks4 = (float4*)k_s;
            float4* vs4 = (float4*)v_s;
#pragma unroll
            for (int i = 0; i < 16; i++) {
                ks4[tid + i * 64] = kp[tid + i * 64];
                vs4[tid + i * 64] = vp[tid + i * 64];
            }
        }
        __syncthreads();

        ULL p2[32];
        float mt = m;
#pragma unroll 4
        for (int j = 0; j < 32; j++) {
            const ulonglong2* kr8 = (const ulonglong2*)(k_s + j * 128);
            ULL a0 = 0, a1 = 0, a2 = 0, a3 = 0;
#pragma unroll
            for (int i2 = 0; i2 < 32; i2 += 2) {
                ulonglong2 kv0 = kr8[i2];
                ulonglong2 kv1 = kr8[i2 + 1];
                FMA2(a0, qr2[2 * i2],     kv0.x, a0);
                FMA2(a1, qr2[2 * i2 + 1], kv0.y, a1);
                FMA2(a2, qr2[2 * i2 + 2], kv1.x, a2);
                FMA2(a3, qr2[2 * i2 + 3], kv1.y, a3);
            }
            float2 f0 = upk2(a0), f1 = upk2(a1), f2 = upk2(a2), f3 = upk2(a3);
            float s = ((f0.x + f0.y) + (f1.x + f1.y)) + ((f2.x + f2.y) + (f3.x + f3.y));
            const int sidx = s0 + j;
            if (sidx > t || (t - sidx) > W) s = -1e30f;
            p2[j] = pk2(s, s);
            mt = fmaxf(mt, s);
        }

        const float alpha = __expf(m - mt);
        m = mt;
        float lt = 0.f;
#pragma unroll
        for (int j = 0; j < 32; j++) {
            float sraw = upk2(p2[j]).x;
            float pv = (sraw > -1e29f) ? __expf(sraw - mt) : 0.f;
            lt += pv;
            p2[j] = pk2(pv, pv);
        }
        l = l * alpha + lt;

        {
            const ULL alpha2 = pk2(alpha, alpha);
            ulonglong2* Or8 = (ulonglong2*)(O_s + tid * 132);
            const ulonglong2* vs8 = (const ulonglong2*)v_s;
#pragma unroll 2
            for (int i2 = 0; i2 < 32; i2++) {
                ulonglong2 acc = Or8[i2];
                MUL2(acc.x, acc.x, alpha2);
                MUL2(acc.y, acc.y, alpha2);
#pragma unroll
                for (int j = 0; j < 32; j++) {
                    ulonglong2 vv = vs8[j * 32 + i2];
                    FMA2(acc.x, p2[j], vv.x, acc.x);
                    FMA2(acc.y, p2[j], vv.y, acc.y);
                }
                Or8[i2] = acc;
            }
        }
        __syncthreads();
    }

    const float inv_l = __fdividef(1.f, l);
    float4* yo = (float4*)(y + qbase + (size_t)tid * R_);
    const float4* Or4 = (const float4*)(O_s + tid * 132);
#pragma unroll
    for (int d4 = 0; d4 < 32; d4++) {
        float4 o = Or4[d4];
        yo[d4] = make_float4(tf32f(o.x * inv_l), tf32f(o.y * inv_l),
                             tf32f(o.z * inv_l), tf32f(o.w * inv_l));
    }
}

// ---------------------------------------------------------------------------
// Host launcher
// ---------------------------------------------------------------------------
extern "C" void kernel_launch(void* const* d_in, const int* in_sizes, int n_in,
                              void* d_out, int out_size) {
    const float* x    = (const float*)d_in[0];
    const float* Uq   = (const float*)d_in[1];
    const float* Uk   = (const float*)d_in[2];
    const float* Uv   = (const float*)d_in[3];
    const float* cosp = (const float*)d_in[4];
    const float* sinp = (const float*)d_in[5];
    const float* ln1w = (const float*)d_in[6];
    const float* ln2w = (const float*)d_in[7];
    const float* Wo   = (const float*)d_in[8];
    const float* w1   = (const float*)d_in[9];
    const float* w3   = (const float*)d_in[10];
    const float* w2   = (const float*)d_in[11];
    const int*   win  = (const int*)d_in[12];
    float* out = (float*)d_out;

    float *normed, *q, *k, *v, *y, *h, *t1;
    float *wq, *wk, *wv, *wo, *w1r, *w3r, *w2r;
    cudaGetSymbolAddress((void**)&normed, g_normed);
    cudaGetSymbolAddress((void**)&q, g_q);
    cudaGetSymbolAddress((void**)&k, g_k);
    cudaGetSymbolAddress((void**)&v, g_v);
    cudaGetSymbolAddress((void**)&y, g_y);
    cudaGetSymbolAddress((void**)&h, g_h);
    cudaGetSymbolAddress((void**)&t1, g_t1);
    cudaGetSymbolAddress((void**)&wq, g_wq);
    cudaGetSymbolAddress((void**)&wk, g_wk);
    cudaGetSymbolAddress((void**)&wv, g_wv);
    cudaGetSymbolAddress((void**)&wo, g_wo);
    cudaGetSymbolAddress((void**)&w1r, g_w1);
    cudaGetSymbolAddress((void**)&w3r, g_w3);
    cudaGetSymbolAddress((void**)&w2r, g_w2);

    cudaFuncSetAttribute(attn_kernel, cudaFuncAttributeMaxDynamicSharedMemorySize,
                         ATTN_SMEM_BYTES);
    cudaFuncSetAttribute(tfgemm_kernel<0>, cudaFuncAttributeMaxDynamicSharedMemorySize,
                         GEMM_SMEM_BYTES);
    cudaFuncSetAttribute(tfgemm_kernel<1>, cudaFuncAttributeMaxDynamicSharedMemorySize,
                         GEMM_SMEM_BYTES);
    cudaFuncSetAttribute(qkv_kernel, cudaFuncAttributeMaxDynamicSharedMemorySize,
                         GEMM_SMEM_BYTES);
    cudaFuncSetAttribute(ffn13_kernel, cudaFuncAttributeMaxDynamicSharedMemorySize,
                         GEMM_SMEM_BYTES);

    // launch 1: fused weight prep
    prep_kernel<<<PREP_TOTAL / 256, 256>>>(
        (const float4*)Uq, (const float4*)Uk, (const float4*)Uv, (const float4*)Wo,
        (const float4*)w1, (const float4*)w3, (const float4*)w2,
        (float4*)wq, (float4*)wk, (float4*)wv, (float4*)wo,
        (float4*)w1r, (float4*)w3r, (float4*)w2r);

    // launch 2: normed = tf32(rmsnorm(x, ln1_w))
    rmsnorm_kernel<<<BT_, 256>>>(x, ln1w, normed);

    // launch 3: fused q,k,v projections
    qkv_kernel<<<dim3(3, BT_ / 128), 256, GEMM_SMEM_BYTES>>>(normed, wq, wk, wv, q, k, v, BT_, D_);

    // launch 4: RoPE
    rope_kernel<<<BT_, 64>>>(q, k, cosp, sinp);

    // launch 5: attention -> y (tf32-rounded)
    attn_kernel<<<dim3(T_ / 64, B_), 64, ATTN_SMEM_BYTES>>>(q, k, v, y, win);

    // launch 6: out = x + y @ Wo^T
    tfgemm_kernel<1><<<dim3(D_ / 128, BT_ / 128), 256, GEMM_SMEM_BYTES>>>(y, wo, x, out, BT_, D_, R_);

    // launch 7: h = tf32(rmsnorm(out, ln2_w))
    rmsnorm_kernel<<<BT_, 256>>>(out, ln2w, h);

    // launch 8: t1 = tf32( (h@w1^T) * silu(h@w3^T) )   -- fused, no round trip
    ffn13_kernel<<<dim3(DFF_ / 64, BT_ / 128), 256, GEMM_SMEM_BYTES>>>(
        h, w1r, w3r, t1, BT_, DFF_, D_);

    // launch 9: out = out + t1 @ w2^T
    tfgemm_kernel<1><<<dim3(D_ / 128, BT_ / 128), 256, GEMM_SMEM_BYTES>>>(t1, w2r, out, out, BT_, D_, DFF_);
}